// round 3
// baseline (speedup 1.0000x reference)
#include <cuda_runtime.h>

// Problem constants
#define T_STEPS 500
#define BATCH   1024
#define NDIM    256
#define ALPHA_F 0.995f   // 1 - 0.05/10
#define VTH_F   1.0f

// Producer/consumer chunking
#define CHUNK_T    20
#define N_CHUNKS   (T_STEPS / CHUNK_T)        // 25
#define TPB        256
#define P_BLOCKS   128                         // producer blocks
#define C_BLOCKS   4                           // consumer blocks (4*256 = 1024 chains)
#define PROD_WARPS (P_BLOCKS * (TPB / 32))     // 1024 == BATCH (each warp owns one b)
#define RBATCH     5                           // rows per producer load batch (20 % 5 == 0)

// Scratch: per-(t,b) input currents (2 MB, L2-resident) + sync flags
__device__ float    g_s[T_STEPS * BATCH];
__device__ unsigned g_flag[N_CHUNKS];   // #producer blocks done with chunk c
__device__ unsigned g_done[N_CHUNKS];   // #consumer blocks done with chunk c (for self-clean)

__device__ __forceinline__ unsigned ld_acquire_gpu(const unsigned* p) {
    unsigned v;
    asm volatile("ld.acquire.gpu.u32 %0, [%1];" : "=r"(v) : "l"(p) : "memory");
    return v;
}

__global__ void __launch_bounds__(TPB) lif_fused_kernel(
    const float* __restrict__ x,      // [T, B, N]
    const float* __restrict__ w,      // [N]
    float* __restrict__ out)          // [2, T, B]  (v then z)
{
    const int tid = threadIdx.x;

    if (blockIdx.x < P_BLOCKS) {
        // ================= PRODUCER =================
        const int warp = tid >> 5;
        const int lane = tid & 31;
        const int gw   = blockIdx.x * (TPB / 32) + warp;   // 0..1023 == batch index b

        // per-lane slice of w (elements lane*4.. and 128+lane*4..)
        const float4* wv = reinterpret_cast<const float4*>(w);
        const float4 w0 = wv[lane];
        const float4 w1 = wv[lane + 32];

        for (int c = 0; c < N_CHUNKS; ++c) {
            const int tbase = c * CHUNK_T;

            #pragma unroll 1
            for (int i0 = 0; i0 < CHUNK_T; i0 += RBATCH) {
                float4 a[2 * RBATCH];
                // issue 2*RBATCH independent float4 loads (streams HBM)
                #pragma unroll
                for (int i = 0; i < RBATCH; ++i) {
                    const long long row = (long long)(tbase + i0 + i) * BATCH + gw;
                    const float4* xr = reinterpret_cast<const float4*>(x + row * NDIM);
                    a[2 * i]     = xr[lane];
                    a[2 * i + 1] = xr[lane + 32];
                }
                // reduce each row; independent trees interleave for ILP
                #pragma unroll
                for (int i = 0; i < RBATCH; ++i) {
                    const float4 p0 = a[2 * i], p1 = a[2 * i + 1];
                    float acc = p0.x * w0.x + p0.y * w0.y + p0.z * w0.z + p0.w * w0.w
                              + p1.x * w1.x + p1.y * w1.y + p1.z * w1.z + p1.w * w1.w;
                    #pragma unroll
                    for (int off = 16; off > 0; off >>= 1)
                        acc += __shfl_xor_sync(0xffffffffu, acc, off);
                    if (lane == 0)
                        g_s[(tbase + i0 + i) * BATCH + gw] = acc;
                }
            }

            __syncthreads();                 // all 8 warps of this block done with chunk c
            if (tid == 0) {
                __threadfence();             // publish g_s writes (release)
                atomicAdd(&g_flag[c], 1u);
            }
        }
    } else {
        // ================= CONSUMER =================
        const int b = (blockIdx.x - P_BLOCKS) * TPB + tid;   // 0..1023
        float* __restrict__ vout = out;                                // [T, B]
        float* __restrict__ zout = out + (long long)T_STEPS * BATCH;   // [T, B]

        float v = 0.0f, z = 0.0f;

        for (int c = 0; c < N_CHUNKS; ++c) {
            if (tid == 0) {
                while (ld_acquire_gpu(&g_flag[c]) < P_BLOCKS) { }
            }
            __syncthreads();   // all threads ordered after the acquire

            const int tbase = c * CHUNK_T;

            // batch all 20 loads before any store (L2 hits, overlapped)
            float s[CHUNK_T];
            #pragma unroll
            for (int i = 0; i < CHUNK_T; ++i)
                s[i] = g_s[(tbase + i) * BATCH + b];

            #pragma unroll
            for (int i = 0; i < CHUNK_T; ++i) {
                v = ALPHA_F * v + s[i] - z;
                z = (v > VTH_F) ? 1.0f : 0.0f;
                const int t = tbase + i;
                vout[(long long)t * BATCH + b] = v;
                zout[(long long)t * BATCH + b] = z;
            }

            __syncthreads();
            // self-clean flags for the next graph replay: last consumer block
            // through chunk c resets (everyone has passed the wait already).
            if (tid == 0) {
                if (atomicAdd(&g_done[c], 1u) == C_BLOCKS - 1) {
                    g_flag[c] = 0;
                    g_done[c] = 0;
                }
            }
        }
    }
}

// ---------------------------------------------------------------------------
extern "C" void kernel_launch(void* const* d_in, const int* in_sizes, int n_in,
                              void* d_out, int out_size)
{
    const float* x = (const float*)d_in[0];   // [T, B, N] fp32
    const float* w = (const float*)d_in[1];   // [N] fp32
    float* out = (float*)d_out;               // [2, T, B] fp32

    lif_fused_kernel<<<P_BLOCKS + C_BLOCKS, TPB>>>(x, w, out);
}

// round 4
// speedup vs baseline: 2.7625x; 2.7625x over previous
#include <cuda_runtime.h>

// Problem constants
#define T_STEPS 500
#define BATCH   1024
#define NDIM    256
#define ALPHA_F 0.995f   // 1 - 0.05/10
#define VTH_F   1.0f

// Producer/consumer chunking
#define CHUNK_T     20
#define N_CHUNKS    (T_STEPS / CHUNK_T)     // 25
#define ROWS_CHUNK  (CHUNK_T * BATCH)       // 20480 rows per chunk
#define TPB         256
#define C_BLOCKS    4                       // consumer blocks (first in grid)
#define P_BLOCKS    512                     // producer blocks
#define ROWS_PB     (ROWS_CHUNK / P_BLOCKS) // 40 rows / block / chunk
#define ROWS_PW     (ROWS_PB / (TPB / 32))  // 5 rows / warp / chunk

// Scratch: per-(t,b) input currents (2 MB, L2-resident) + sync flags
__device__ float    g_s[T_STEPS * BATCH];
__device__ unsigned g_flag[N_CHUNKS];   // #producer blocks done with chunk c
__device__ unsigned g_done[N_CHUNKS];   // #consumer blocks done (self-clean)

__device__ __forceinline__ unsigned ld_acquire_gpu(const unsigned* p) {
    unsigned v;
    asm volatile("ld.acquire.gpu.u32 %0, [%1];" : "=r"(v) : "l"(p) : "memory");
    return v;
}

__global__ void __launch_bounds__(TPB) lif_fused_kernel(
    const float* __restrict__ x,      // [T, B, N]
    const float* __restrict__ w,      // [N]
    float* __restrict__ out)          // [2, T, B]  (v then z)
{
    const int tid = threadIdx.x;

    if (blockIdx.x >= C_BLOCKS) {
        // ================= PRODUCER =================
        // Per chunk: this block owns 40 consecutive rows; each warp owns 5.
        // Same per-warp structure as the roofline-proven standalone GEMV:
        // 10 independent float4 loads, then 5 interleaved shfl-reduce trees.
        const int pb   = blockIdx.x - C_BLOCKS;        // 0..511
        const int warp = tid >> 5;
        const int lane = tid & 31;

        const float4* wv = reinterpret_cast<const float4*>(w);
        const float4 w0 = wv[lane];
        const float4 w1 = wv[lane + 32];

        for (int c = 0; c < N_CHUNKS; ++c) {
            const long long rbase = (long long)c * ROWS_CHUNK
                                  + pb * ROWS_PB + warp * ROWS_PW;

            float4 a[2 * ROWS_PW];
            #pragma unroll
            for (int i = 0; i < ROWS_PW; ++i) {
                const float4* xr =
                    reinterpret_cast<const float4*>(x + (rbase + i) * NDIM);
                a[2 * i]     = xr[lane];
                a[2 * i + 1] = xr[lane + 32];
            }

            float acc[ROWS_PW];
            #pragma unroll
            for (int i = 0; i < ROWS_PW; ++i) {
                const float4 p0 = a[2 * i], p1 = a[2 * i + 1];
                acc[i] = p0.x * w0.x + p0.y * w0.y + p0.z * w0.z + p0.w * w0.w
                       + p1.x * w1.x + p1.y * w1.y + p1.z * w1.z + p1.w * w1.w;
            }
            // interleave the 5 reduce trees level-by-level for ILP
            #pragma unroll
            for (int off = 16; off > 0; off >>= 1) {
                #pragma unroll
                for (int i = 0; i < ROWS_PW; ++i)
                    acc[i] += __shfl_xor_sync(0xffffffffu, acc[i], off);
            }
            if (lane == 0) {
                #pragma unroll
                for (int i = 0; i < ROWS_PW; ++i)
                    g_s[rbase + i] = acc[i];
            }

            __syncthreads();               // all warps of this block done with chunk c
            if (tid == 0) {
                __threadfence();           // publish g_s writes (release)
                atomicAdd(&g_flag[c], 1u);
            }
        }
    } else {
        // ================= CONSUMER =================
        const int b = blockIdx.x * TPB + tid;   // 0..1023
        float* __restrict__ vout = out;                               // [T, B]
        float* __restrict__ zout = out + (long long)T_STEPS * BATCH;  // [T, B]

        float v = 0.0f, z = 0.0f;

        for (int c = 0; c < N_CHUNKS; ++c) {
            if (tid == 0) {
                while (ld_acquire_gpu(&g_flag[c]) < P_BLOCKS) { }
            }
            __syncthreads();   // order all threads after the acquire

            const int tbase = c * CHUNK_T;

            float s[CHUNK_T];
            #pragma unroll
            for (int i = 0; i < CHUNK_T; ++i)
                s[i] = g_s[(tbase + i) * BATCH + b];

            #pragma unroll
            for (int i = 0; i < CHUNK_T; ++i) {
                v = ALPHA_F * v + s[i] - z;
                z = (v > VTH_F) ? 1.0f : 0.0f;
                const int t = tbase + i;
                vout[(long long)t * BATCH + b] = v;
                zout[(long long)t * BATCH + b] = z;
            }

            __syncthreads();
            // self-clean flags for next graph replay: last consumer block resets
            if (tid == 0) {
                if (atomicAdd(&g_done[c], 1u) == C_BLOCKS - 1) {
                    g_flag[c] = 0;
                    g_done[c] = 0;
                }
            }
        }
    }
}

// ---------------------------------------------------------------------------
extern "C" void kernel_launch(void* const* d_in, const int* in_sizes, int n_in,
                              void* d_out, int out_size)
{
    const float* x = (const float*)d_in[0];   // [T, B, N] fp32
    const float* w = (const float*)d_in[1];   // [N] fp32
    float* out = (float*)d_out;               // [2, T, B] fp32

    lif_fused_kernel<<<P_BLOCKS + C_BLOCKS, TPB>>>(x, w, out);
}